// round 9
// baseline (speedup 1.0000x reference)
#include <cuda_runtime.h>

#define BN 64
#define TN 512
#define LN 48
#define CL 32            // chunk length (steps)
#define NC 16            // chunks per batch = TN/CL
#define START_I 46
#define PAD_I 45
#define END_I 47

__device__ float g_dir[BN][NC][LN];   // boundary directions (slot c: output of chunk c)
__device__ unsigned g_flag[BN][NC];   // zero-init; consumer resets after read
__device__ float g_S[BN][NC];         // per-chunk log-magnitudes
__device__ float g_tailEND[BN];       // log(d_END) of last chunk
__device__ float g_tg[BN];
__device__ float g_val[BN];
__device__ unsigned g_bd[BN];         // per-batch arrival counters (self-reset)
__device__ unsigned g_done;           // global arrival counter (self-reset)

#define FMA_F32X2(d, a, b, c) \
    asm("fma.rn.f32x2 %0, %1, %2, %3;" : "=l"(d) : "l"(a), "l"(b), "l"(c))
#define ADD_F32X2_(d, a, b) \
    asm("add.rn.f32x2 %0, %1, %2;" : "=l"(d) : "l"(a), "l"(b))
#define PACK_F32X2_(d, lo, hi) \
    asm("mov.b64 %0, {%1, %2};" : "=l"(d) : "f"(lo), "f"(hi))
#define UNPACK_F32X2_(lo, hi, s) \
    asm("mov.b64 {%0, %1}, %2;" : "=f"(lo), "=f"(hi) : "l"(s))

// Validated CL-step scan. u in scaled linear domain: u_j = exp(fs_j - K*ln2).
__device__ __forceinline__ float chunk_scan(
    const float* __restrict__ scp, const int* __restrict__ mp,
    const unsigned long long* Ep, float u, bool act, int tid,
    float sh_w[2][LN], int sh_k[2], int* K_out)
{
    int K = 0, kcur = 0;
    if (tid == 0) { sh_k[0] = 0; sh_k[1] = 0; }

    float es[4];
    int   mb[4];
#pragma unroll
    for (int q = 0; q < 4; q++) { es[q] = __expf(scp[q * LN]); mb[q] = mp[q]; }

    float w = u * es[0];
    __syncthreads();

    for (int t0 = 0; t0 < CL; t0 += 4) {
#pragma unroll
        for (int k = 0; k < 4; k++) {
            const int t = t0 + k;
            const int p = t & 1;
            const int msk = mb[k];

            if (act) sh_w[p][tid] = w;
            __syncthreads();

            const int knext = sh_k[p ^ 1];
            const float esn = es[(k + 1) & 3] *
                              __int_as_float((127 - knext) << 23);

            K += kcur;
            const float sc_cur = __int_as_float((127 - kcur) << 23);

            const ulonglong2* w2 = (const ulonglong2*)sh_w[p];
            unsigned long long a0 = 0ull, a1 = 0ull, a2 = 0ull, a3 = 0ull;
#pragma unroll
            for (int q = 0; q < LN / 4; q++) {
                const ulonglong2 wq = w2[q];
                if ((q & 1) == 0) {
                    FMA_F32X2(a0, wq.x, Ep[2 * q],     a0);
                    FMA_F32X2(a1, wq.y, Ep[2 * q + 1], a1);
                } else {
                    FMA_F32X2(a2, wq.x, Ep[2 * q],     a2);
                    FMA_F32X2(a3, wq.y, Ep[2 * q + 1], a3);
                }
            }
            unsigned long long s01, s23, s;
            ADD_F32X2_(s01, a0, a1);
            ADD_F32X2_(s23, a2, a3);
            ADD_F32X2_(s, s01, s23);
            float slo, shi;
            UNPACK_F32X2_(slo, shi, s);
            const float accv = slo + shi;

            u = msk ? accv : u * sc_cur;
            if (tid == 0) sh_k[p] = (__float_as_int(u) >> 23) - 127;
            w = u * esn;
            kcur = knext;

            if (t0 + 4 < CL) {
                es[k] = __expf(scp[(t0 + 4 + k) * LN]);
                mb[k] = mp[t0 + 4 + k];
            }
        }
    }
    *K_out = K;
    return u;
}

// L1-sum over sh_w[0] (all threads compute identical value)
__device__ __forceinline__ float sumvec(const float sh[LN])
{
    float sum = 0.f;
    const float4* v4 = (const float4*)sh;
#pragma unroll
    for (int q = 0; q < LN / 4; q++) {
        const float4 v = v4[q];
        sum += (v.x + v.y) + (v.z + v.w);
    }
    return sum;
}

// One CTA per (batch b, chunk c); grid = BN*NC = 1024 = one full wave at 7 CTA/SM
// (guaranteed by launch_bounds), so cross-CTA spin-waits cannot deadlock.
//   c = 0      : single scan from ones (log48 cancels in stitch); publish dir[0].
//   c = 1..14  : scan1 from ones -> publish dir[c]; spin for dir[c-1]; scan2 (L1-hot).
//   c = 15     : tg gold-energy during the wait; spin for dir[14]; scan2; tail.
__global__ __launch_bounds__(64, 7) void crf_fused_kernel(
    const float* __restrict__ scores,
    const void* __restrict__ gold_raw,
    const int* __restrict__ mask,
    const float* __restrict__ trans,
    float* __restrict__ out)
{
    const int bid = blockIdx.x;
    const int b = bid >> 4;
    const int c = bid & (NC - 1);
    const int tid = threadIdx.x;
    const bool act = (tid < LN);
    const int j = act ? tid : 0;

    __shared__ float sh_w[2][LN];
    __shared__ int sh_k[2];
    __shared__ float sh_tgp[2];
    __shared__ int sh_is64;

    // E column j, packed as 24 f32x2 pairs; exp(-10000) == 0
    unsigned long long Ep[LN / 2];
#pragma unroll
    for (int q = 0; q < LN / 2; q++) {
        float lo = __expf(trans[(2 * q) * LN + j]);
        float hi = __expf(trans[(2 * q + 1) * LN + j]);
        PACK_F32X2_(Ep[q], lo, hi);
    }

    const float* scp = scores + ((size_t)b * TN + c * CL) * LN + j;
    const int*   mp  = mask + (size_t)b * TN + c * CL;

    if (c == NC - 1) {
        // ---- tg gold-path energy for batch b (overlaps the dir[14] wait) ----
        // gold declared int64; JAX (x64 off) materializes int32 — detect (warp 0):
        // true int64 => every odd 32-bit word is 0 (labels < 48).
        const int* g32 = (const int*)gold_raw;
        if (tid < 32) {
            const int ok = (g32[2 * tid + 1] == 0) && (g32[2 * (tid + 32) + 1] == 0);
            const unsigned bl = __ballot_sync(0xffffffffu, ok);
            if (tid == 0) sh_is64 = (bl == 0xffffffffu);
        }
        __syncthreads();
        const int is64 = sh_is64;

        float sum = 0.f;
#pragma unroll
        for (int t = tid; t < TN; t += 64) {
            const long long li = (long long)b * TN + t;
            const int g = is64 ? g32[2 * li] : g32[li];   // little-endian low word
            const float v = scores[li * LN] + trans[g];   // crf[t+1,b,0,g]
            if (mask[li]) sum += v;
        }
        if (tid == 0) sum += trans[START_I];              // t=0 term: trans[0][START]

        sum += __shfl_xor_sync(0xffffffffu, sum, 16);
        sum += __shfl_xor_sync(0xffffffffu, sum, 8);
        sum += __shfl_xor_sync(0xffffffffu, sum, 4);
        sum += __shfl_xor_sync(0xffffffffu, sum, 2);
        sum += __shfl_xor_sync(0xffffffffu, sum, 1);
        if ((tid & 31) == 0) sh_tgp[tid >> 5] = sum;
        __syncthreads();
        if (tid == 0) { g_tg[b] = sh_tgp[0] + sh_tgp[1]; }
        __threadfence();
    }

    float S;
    if (c == 0) {
        int K;
        const float u = chunk_scan(scp, mp, Ep, 1.0f, act, tid, sh_w, sh_k, &K);
        if (act) sh_w[0][tid] = u;
        __syncthreads();
        const float sum = sumvec(sh_w[0]);
        if (act) g_dir[b][0][tid] = u / sum;
        __threadfence();
        __syncthreads();
        if (tid == 0) g_flag[b][0] = 1u;
        S = (float)K * 0.6931471805599453f + logf(sum);
    } else {
        if (c < NC - 1) {
            int K1;
            const float u1 = chunk_scan(scp, mp, Ep, 1.0f, act, tid, sh_w, sh_k, &K1);
            if (act) sh_w[0][tid] = u1;
            __syncthreads();
            const float sum1 = sumvec(sh_w[0]);
            if (act) g_dir[b][c][tid] = u1 / sum1;
            __threadfence();
            __syncthreads();
            if (tid == 0) g_flag[b][c] = 1u;
        }

        // spin-wait for predecessor's direction (resident producer -> resolves)
        if (tid == 0) {
            volatile unsigned* f = &g_flag[b][c - 1];
            while (*f == 0u) __nanosleep(64);
            *f = 0u;                // single consumer; reset for next graph replay
            __threadfence();
        }
        __syncthreads();

        const float u0 = g_dir[b][c - 1][j];
        int K;
        const float u = chunk_scan(scp, mp, Ep, u0, act, tid, sh_w, sh_k, &K);
        if (act) sh_w[0][tid] = u;
        __syncthreads();
        const float sum = sumvec(sh_w[0]);
        S = (float)K * 0.6931471805599453f + logf(sum);
        if (c == NC - 1 && tid == END_I) g_tailEND[b] = logf(u) - logf(sum);
    }

    if (tid == 0) g_S[b][c] = S;
    __threadfence();           // every thread fences its own global writes
    __syncthreads();

    if (tid == 0) {
        const unsigned r = atomicAdd(&g_bd[b], 1u);
        if (r == NC - 1) {              // last chunk of batch b: stitch
            __threadfence();
            float fs = g_tailEND[b];    // log48 cancelled against scan-from-ones S_0
            for (int c2 = 0; c2 < NC; c2++) fs += g_S[b][c2];
            g_val[b] = fs - g_tg[b];
            g_bd[b] = 0u;               // reset for next graph replay
            __threadfence();
            const unsigned r2 = atomicAdd(&g_done, 1u);
            if (r2 == BN - 1) {         // last batch: deterministic final combine
                __threadfence();
                float acc = 0.f;
                for (int i = 0; i < BN; i++) acc += g_val[i];
                out[0] = acc / (float)BN;
                g_done = 0u;            // reset for next graph replay
            }
        }
    }
}

extern "C" void kernel_launch(void* const* d_in, const int* in_sizes, int n_in,
                              void* d_out, int out_size)
{
    const float* scores = (const float*)d_in[0];
    const void*  gold   = (const void*)d_in[1];
    const int*   mask   = (const int*)d_in[2];
    const float* trans  = (const float*)d_in[3];
    float*       out    = (float*)d_out;

    crf_fused_kernel<<<BN * NC, 64>>>(scores, gold, mask, trans, out);
}

// round 10
// speedup vs baseline: 1.4723x; 1.4723x over previous
#include <cuda_runtime.h>

#define BN 64
#define TN 512
#define LN 48
#define CL 32            // chunk length (steps)
#define NC 16            // chunks per batch = TN/CL
#define START_I 46
#define PAD_I 45
#define END_I 47

__device__ float g_dir[BN][NC - 1][LN];  // pass-1 boundary directions
__device__ float g_S[BN][NC];            // pass-2 per-chunk log-magnitudes
__device__ float g_tailEND[BN];          // log(d_END) of last chunk
__device__ float g_tg[BN];
__device__ float g_val[BN];
__device__ unsigned int g_bd[BN];        // per-batch arrival counters (self-reset)
__device__ unsigned int g_done;          // global arrival counter (self-reset)

#define FMA_F32X2(d, a, b, c) \
    asm("fma.rn.f32x2 %0, %1, %2, %3;" : "=l"(d) : "l"(a), "l"(b), "l"(c))
#define ADD_F32X2_(d, a, b) \
    asm("add.rn.f32x2 %0, %1, %2;" : "=l"(d) : "l"(a), "l"(b))
#define PACK_F32X2_(d, lo, hi) \
    asm("mov.b64 %0, {%1, %2};" : "=l"(d) : "f"(lo), "f"(hi))
#define UNPACK_F32X2_(lo, hi, s) \
    asm("mov.b64 {%0, %1}, %2;" : "=f"(lo), "=f"(hi) : "l"(s))

// Single-warp CL-step scan; NO block barrier — __syncwarp only.
// Lane t < 24 owns columns (2t, 2t+1): u0/u1 in scaled linear domain.
// Ea/Eb: per-column E packed over i-pairs (24 f32x2 each).
__device__ __forceinline__ void chunk_scan_w1(
    const float* __restrict__ scp,      // scores chunk base + own pair offset
    const int* __restrict__ mp,
    const unsigned long long* Ea, const unsigned long long* Eb,
    float& u0, float& u1, bool act, int lane,
    float sh_w[2][LN], int sh_k[2], int* K_out)
{
    int K = 0, kcur = 0;
    if (lane == 0) { sh_k[0] = 0; sh_k[1] = 0; }

    float es0[4], es1[4];
    int mb[4];
#pragma unroll
    for (int q = 0; q < 4; q++) {
        const float2 sv = *(const float2*)(scp + q * LN);
        es0[q] = __expf(sv.x);
        es1[q] = __expf(sv.y);
        mb[q] = mp[q];
    }

    float w0 = u0 * es0[0], w1 = u1 * es1[0];
    __syncwarp();

    for (int t0 = 0; t0 < CL; t0 += 4) {
#pragma unroll
        for (int k = 0; k < 4; k++) {
            const int t = t0 + k;
            const int p = t & 1;
            const int msk = mb[k];

            if (act) {
                unsigned long long wp;
                PACK_F32X2_(wp, w0, w1);
                *(unsigned long long*)&sh_w[p][2 * lane] = wp;  // STS.64
            }
            __syncwarp();

            const int knext = sh_k[p ^ 1];
            const float scn = __int_as_float((127 - knext) << 23);
            K += kcur;
            const float sc_cur = __int_as_float((127 - kcur) << 23);

            // two column dot-products: 12 LDS.128 (broadcast) + 48 FFMA2
            const ulonglong2* w2 = (const ulonglong2*)sh_w[p];
            unsigned long long a0 = 0ull, a1 = 0ull, a2 = 0ull, a3 = 0ull;
            unsigned long long b0 = 0ull, b1 = 0ull, b2 = 0ull, b3 = 0ull;
#pragma unroll
            for (int q = 0; q < LN / 4; q++) {
                const ulonglong2 wq = w2[q];
                if ((q & 1) == 0) {
                    FMA_F32X2(a0, wq.x, Ea[2 * q],     a0);
                    FMA_F32X2(a1, wq.y, Ea[2 * q + 1], a1);
                    FMA_F32X2(b0, wq.x, Eb[2 * q],     b0);
                    FMA_F32X2(b1, wq.y, Eb[2 * q + 1], b1);
                } else {
                    FMA_F32X2(a2, wq.x, Ea[2 * q],     a2);
                    FMA_F32X2(a3, wq.y, Ea[2 * q + 1], a3);
                    FMA_F32X2(b2, wq.x, Eb[2 * q],     b2);
                    FMA_F32X2(b3, wq.y, Eb[2 * q + 1], b3);
                }
            }
            unsigned long long sA, sB, x, y;
            ADD_F32X2_(x, a0, a1);
            ADD_F32X2_(y, a2, a3);
            ADD_F32X2_(sA, x, y);
            ADD_F32X2_(x, b0, b1);
            ADD_F32X2_(y, b2, b3);
            ADD_F32X2_(sB, x, y);
            float lo, hi;
            UNPACK_F32X2_(lo, hi, sA);
            const float acc0 = lo + hi;
            UNPACK_F32X2_(lo, hi, sB);
            const float acc1 = lo + hi;

            u0 = msk ? acc0 : u0 * sc_cur;
            u1 = msk ? acc1 : u1 * sc_cur;

            if (lane == 0) sh_k[p] = (__float_as_int(u0) >> 23) - 127;  // column 0

            w0 = u0 * es0[(k + 1) & 3] * scn;
            w1 = u1 * es1[(k + 1) & 3] * scn;
            kcur = knext;

            if (t0 + 4 < CL) {
                const float2 sv = *(const float2*)(scp + (t0 + 4 + k) * LN);
                es0[k] = __expf(sv.x);
                es1[k] = __expf(sv.y);
                mb[k] = mp[t0 + 4 + k];
            }
        }
    }
    *K_out = K;
}

// L1-sum over 48 positive floats (all lanes compute identical value)
__device__ __forceinline__ float sumvec(const float sh[LN])
{
    float sum = 0.f;
    const float4* v4 = (const float4*)sh;
#pragma unroll
    for (int q = 0; q < LN / 4; q++) {
        const float4 v = v4[q];
        sum += (v.x + v.y) + (v.z + v.w);
    }
    return sum;
}

// build packed E columns for this lane's pair
__device__ __forceinline__ void build_E(
    const float* __restrict__ trans, int j0, int j1,
    unsigned long long* Ea, unsigned long long* Eb)
{
#pragma unroll
    for (int q = 0; q < LN / 2; q++) {
        float lo = __expf(trans[(2 * q) * LN + j0]);
        float hi = __expf(trans[(2 * q + 1) * LN + j0]);
        PACK_F32X2_(Ea[q], lo, hi);
        lo = __expf(trans[(2 * q) * LN + j1]);
        hi = __expf(trans[(2 * q + 1) * LN + j1]);
        PACK_F32X2_(Eb[q], lo, hi);
    }
}

// Pass 1: bid < BN*(NC-1): chunk c of batch b from all-ones -> store direction.
//         bid >= BN*(NC-1): gold-path energy for batch (bid - offset).
__global__ __launch_bounds__(32) void crf_pass1_kernel(
    const float* __restrict__ scores,
    const void* __restrict__ gold_raw,
    const int* __restrict__ mask,
    const float* __restrict__ trans)
{
    const int bid = blockIdx.x;
    const int lane = threadIdx.x;

    __shared__ float sh_w[2][LN];
    __shared__ int sh_k[2];

    if (bid < BN * (NC - 1)) {
        const int b = bid / (NC - 1);
        const int c = bid % (NC - 1);
        const bool act = (lane < LN / 2);
        const int j0 = act ? 2 * lane : 0;
        const int j1 = act ? 2 * lane + 1 : 0;

        unsigned long long Ea[LN / 2], Eb[LN / 2];
        build_E(trans, j0, j1, Ea, Eb);

        const float* scp = scores + ((size_t)b * TN + c * CL) * LN + j0;
        const int*   mp  = mask + (size_t)b * TN + c * CL;

        float u0 = 1.0f, u1 = 1.0f;
        int K;
        chunk_scan_w1(scp, mp, Ea, Eb, u0, u1, act, lane, sh_w, sh_k, &K);

        if (act) {
            unsigned long long up;
            PACK_F32X2_(up, u0, u1);
            *(unsigned long long*)&sh_w[0][2 * lane] = up;
        }
        __syncwarp();
        const float sum = sumvec(sh_w[0]);
        if (act) {
            float2* dp = (float2*)&g_dir[b][c][2 * lane];
            *dp = make_float2(u0 / sum, u1 / sum);
        }
    } else {
        // ---- gold-path energy (one warp per batch) ----
        const int b = bid - BN * (NC - 1);

        // gold declared int64; JAX (x64 off) materializes int32 — detect via ballot:
        // true int64 => every odd 32-bit word is 0 (labels < 48).
        const int* g32 = (const int*)gold_raw;
        const int ok = (g32[2 * lane + 1] == 0) && (g32[2 * (lane + 32) + 1] == 0);
        const int is64 = (__ballot_sync(0xffffffffu, ok) == 0xffffffffu);

        float sum = 0.f;
#pragma unroll
        for (int t = lane; t < TN; t += 32) {
            const long long li = (long long)b * TN + t;
            const int g = is64 ? g32[2 * li] : g32[li];   // little-endian low word
            const float v = scores[li * LN] + trans[g];   // crf[t+1,b,0,g]
            if (mask[li]) sum += v;
        }
        if (lane == 0) sum += trans[START_I];             // t=0 term: trans[0][START]

        sum += __shfl_xor_sync(0xffffffffu, sum, 16);
        sum += __shfl_xor_sync(0xffffffffu, sum, 8);
        sum += __shfl_xor_sync(0xffffffffu, sum, 4);
        sum += __shfl_xor_sync(0xffffffffu, sum, 2);
        sum += __shfl_xor_sync(0xffffffffu, sum, 1);
        if (lane == 0) g_tg[b] = sum;
    }
}

// Pass 2: chunk c of batch b from the pass-1 boundary direction (c=0: true init
// ones/48 — exact since trans[START,:]=0). Magnitudes compose exactly.
__global__ __launch_bounds__(32) void crf_pass2_kernel(
    const float* __restrict__ scores,
    const int* __restrict__ mask,
    const float* __restrict__ trans,
    float* __restrict__ out)
{
    const int bid = blockIdx.x;
    const int b = bid >> 4;
    const int c = bid & (NC - 1);
    const int lane = threadIdx.x;
    const bool act = (lane < LN / 2);
    const int j0 = act ? 2 * lane : 0;
    const int j1 = act ? 2 * lane + 1 : 0;

    __shared__ float sh_w[2][LN];
    __shared__ int sh_k[2];

    unsigned long long Ea[LN / 2], Eb[LN / 2];
    build_E(trans, j0, j1, Ea, Eb);

    float u0, u1;
    if (c == 0) {
        u0 = 1.0f / 48.0f;
        u1 = 1.0f / 48.0f;
    } else {
        const float2 dv = *(const float2*)&g_dir[b][c - 1][j0];
        u0 = dv.x;
        u1 = dv.y;
    }

    const float* scp = scores + ((size_t)b * TN + c * CL) * LN + j0;
    const int*   mp  = mask + (size_t)b * TN + c * CL;

    int K;
    chunk_scan_w1(scp, mp, Ea, Eb, u0, u1, act, lane, sh_w, sh_k, &K);

    if (act) {
        unsigned long long up;
        PACK_F32X2_(up, u0, u1);
        *(unsigned long long*)&sh_w[0][2 * lane] = up;
    }
    __syncwarp();
    const float sum = sumvec(sh_w[0]);

    if (c == NC - 1 && lane == (END_I >> 1))   // lane 23 owns column 47 = END
        g_tailEND[b] = logf(u1) - logf(sum);

    if (lane == 0) {
        g_S[b][c] = (float)K * 0.6931471805599453f + logf(sum);
        __threadfence();
        const unsigned r = atomicAdd(&g_bd[b], 1u);
        if (r == NC - 1) {                 // last chunk of batch b: stitch
            __threadfence();
            float fs = 3.8712010109078911f + g_tailEND[b];   // log(48) + tail
            for (int c2 = 0; c2 < NC; c2++) fs += g_S[b][c2];
            g_val[b] = fs - g_tg[b];
            g_bd[b] = 0u;                  // reset for next graph replay
            __threadfence();
            const unsigned r2 = atomicAdd(&g_done, 1u);
            if (r2 == BN - 1) {            // last batch: deterministic final combine
                __threadfence();
                float acc = 0.f;
                for (int i = 0; i < BN; i++) acc += g_val[i];
                out[0] = acc / (float)BN;
                g_done = 0u;               // reset for next graph replay
            }
        }
    }
}

extern "C" void kernel_launch(void* const* d_in, const int* in_sizes, int n_in,
                              void* d_out, int out_size)
{
    const float* scores = (const float*)d_in[0];
    const void*  gold   = (const void*)d_in[1];
    const int*   mask   = (const int*)d_in[2];
    const float* trans  = (const float*)d_in[3];
    float*       out    = (float*)d_out;

    crf_pass1_kernel<<<BN * (NC - 1) + BN, 32>>>(scores, gold, mask, trans);
    crf_pass2_kernel<<<BN * NC, 32>>>(scores, mask, trans, out);
}